// round 15
// baseline (speedup 1.0000x reference)
#include <cuda_runtime.h>
#include <cuda_bf16.h>
#include <cstdint>

// ---------------------------------------------------------------------------
// Problem constants
// ---------------------------------------------------------------------------
#define BATCH 4
#define LSEQ  2048
#define CDIM  1024
#define NHEAD 16
#define DHEAD 64
#define MROWS (BATCH * LSEQ)   // 8192
#define KDIM  1024

// ---------------------------------------------------------------------------
// Device-global scratch (allocation-free per harness rules)
// ---------------------------------------------------------------------------
__device__ __nv_bfloat16 g_in_h [MROWS * KDIM];
__device__ __nv_bfloat16 g_in_l [MROWS * KDIM];
__device__ __nv_bfloat16 g_win_h[3 * CDIM * KDIM];
__device__ __nv_bfloat16 g_win_l[3 * CDIM * KDIM];
__device__ __nv_bfloat16 g_wout_h[CDIM * KDIM];
__device__ __nv_bfloat16 g_wout_l[CDIM * KDIM];
__device__ __nv_bfloat16 g_qh[BATCH * NHEAD * LSEQ * DHEAD];
__device__ __nv_bfloat16 g_ql[BATCH * NHEAD * LSEQ * DHEAD];
__device__ __nv_bfloat16 g_kh[BATCH * NHEAD * LSEQ * DHEAD];
__device__ __nv_bfloat16 g_kl[BATCH * NHEAD * LSEQ * DHEAD];
__device__ __nv_bfloat16 g_vh[BATCH * NHEAD * LSEQ * DHEAD];
__device__ __nv_bfloat16 g_vl[BATCH * NHEAD * LSEQ * DHEAD];
__device__ __nv_bfloat16 g_ctx_h[MROWS * CDIM];
__device__ __nv_bfloat16 g_ctx_l[MROWS * CDIM];

// ---------------------------------------------------------------------------
// Baseline-PTX helpers (compute_103-safe: mma.sync, ldmatrix, cp.async)
// ---------------------------------------------------------------------------
__device__ __forceinline__ uint32_t smem_u32(const void* p) {
    uint32_t a;
    asm("{ .reg .u64 t; cvta.to.shared.u64 t, %1; cvt.u32.u64 %0, t; }"
        : "=r"(a) : "l"(p));
    return a;
}
__device__ __forceinline__ void ldsm_x4(uint32_t r[4], uint32_t addr) {
    asm volatile("ldmatrix.sync.aligned.m8n8.x4.shared.b16 {%0,%1,%2,%3}, [%4];"
                 : "=r"(r[0]), "=r"(r[1]), "=r"(r[2]), "=r"(r[3]) : "r"(addr));
}
__device__ __forceinline__ void ldsm_x4_t(uint32_t r[4], uint32_t addr) {
    asm volatile("ldmatrix.sync.aligned.m8n8.x4.trans.shared.b16 {%0,%1,%2,%3}, [%4];"
                 : "=r"(r[0]), "=r"(r[1]), "=r"(r[2]), "=r"(r[3]) : "r"(addr));
}
__device__ __forceinline__ void mma_bf16(float c[4],
                                         uint32_t a0, uint32_t a1, uint32_t a2, uint32_t a3,
                                         uint32_t b0, uint32_t b1) {
    asm volatile(
        "mma.sync.aligned.m16n8k16.row.col.f32.bf16.bf16.f32 "
        "{%0,%1,%2,%3}, {%4,%5,%6,%7}, {%8,%9}, {%0,%1,%2,%3};"
        : "+f"(c[0]), "+f"(c[1]), "+f"(c[2]), "+f"(c[3])
        : "r"(a0), "r"(a1), "r"(a2), "r"(a3), "r"(b0), "r"(b1));
}
__device__ __forceinline__ void cp16(uint32_t dst, const void* src) {
    asm volatile("cp.async.cg.shared.global [%0], [%1], 16;" :: "r"(dst), "l"(src));
}
#define CP_COMMIT() asm volatile("cp.async.commit_group;" ::: "memory")
#define CP_WAIT(N)  asm volatile("cp.async.wait_group %0;" :: "n"(N) : "memory")

__device__ __forceinline__ void split_bf16(float x, __nv_bfloat16& h, __nv_bfloat16& l) {
    h = __float2bfloat16(x);
    l = __float2bfloat16(x - __bfloat162float(h));
}
__device__ __forceinline__ void pack_split2(float x, float y, uint32_t& hi, uint32_t& lo) {
    __nv_bfloat162 h = __floats2bfloat162_rn(x, y);
    float2 hf = __bfloat1622float2(h);
    __nv_bfloat162 l = __floats2bfloat162_rn(x - hf.x, y - hf.y);
    hi = *(uint32_t*)&h;
    lo = *(uint32_t*)&l;
}

// ---------------------------------------------------------------------------
// fp32 -> (bf16 hi, bf16 lo) conversion — single fused launch, 2 float4/thr.
// ---------------------------------------------------------------------------
#define CVT_N_IN   (MROWS * KDIM / 4)
#define CVT_N_WIN  (3 * CDIM * KDIM / 4)
#define CVT_N_WOUT (CDIM * KDIM / 4)
#define CVT_TOTAL  (CVT_N_IN + CVT_N_WIN + CVT_N_WOUT)

__device__ __forceinline__ void cvt_one(int i,
                                        const float* __restrict__ in,
                                        const float* __restrict__ w_in,
                                        const float* __restrict__ w_out)
{
    const float* src;
    __nv_bfloat16* hp;
    __nv_bfloat16* lp;
    int j;
    if (i < CVT_N_IN) {
        src = in;  hp = g_in_h;  lp = g_in_l;  j = i;
    } else if (i < CVT_N_IN + CVT_N_WIN) {
        src = w_in; hp = g_win_h; lp = g_win_l; j = i - CVT_N_IN;
    } else {
        src = w_out; hp = g_wout_h; lp = g_wout_l; j = i - CVT_N_IN - CVT_N_WIN;
    }
    float4 v = ((const float4*)src)[j];
    __nv_bfloat16 h0, h1, h2, h3, l0, l1, l2, l3;
    split_bf16(v.x, h0, l0); split_bf16(v.y, h1, l1);
    split_bf16(v.z, h2, l2); split_bf16(v.w, h3, l3);
    __nv_bfloat162 a, b;
    a.x = h0; a.y = h1; b.x = h2; b.y = h3;
    *(__nv_bfloat162*)(hp + 4 * (size_t)j)     = a;
    *(__nv_bfloat162*)(hp + 4 * (size_t)j + 2) = b;
    a.x = l0; a.y = l1; b.x = l2; b.y = l3;
    *(__nv_bfloat162*)(lp + 4 * (size_t)j)     = a;
    *(__nv_bfloat162*)(lp + 4 * (size_t)j + 2) = b;
}

__global__ __launch_bounds__(256) void cvt_kernel(const float* __restrict__ in,
                                                  const float* __restrict__ w_in,
                                                  const float* __restrict__ w_out)
{
    const int base = blockIdx.x * 512 + threadIdx.x;
    if (base < CVT_TOTAL) cvt_one(base, in, w_in, w_out);
    if (base + 256 < CVT_TOTAL) cvt_one(base + 256, in, w_in, w_out);
}

// ---------------------------------------------------------------------------
// HMMA split-bf16 NT GEMM, BM=128, BN=128, BK=64, 2-stage cp.async, 1 CTA/SM.
// 256 threads (8 warps, 2x4 grid), warp tile 64x32: 12 LDSM per 48 MMAs.
// Register double-buffered fragments across the 4 ks-steps.
// Per-stage layout (bytes): AH 0, AL 18432, BH 36864, BL 55296; stage 73728.
// ---------------------------------------------------------------------------
#define RSH 72                            // row stride in halves (144 B)
#define G_AL 18432
#define G_BH 36864
#define G_BL 55296
#define G_STAGE 73728
#define SMEM_GEMM (2 * G_STAGE)           // 147456

template <int MODE>
__global__ __launch_bounds__(256, 1) void gemm_hmma(float* __restrict__ Cout)
{
    extern __shared__ __align__(16) char dsm[];
    const uint32_t sbase = smem_u32(dsm);

    const int tid  = threadIdx.x;
    const int wid  = tid >> 5;
    const int lane = tid & 31;
    const int wy = wid >> 2;            // 0..1 (m: 64 rows each)
    const int wx = wid & 3;             // 0..3 (n: 32 cols each)
    const int g = lane >> 2;
    const int t = lane & 3;
    const int m0 = blockIdx.y * 128;
    const int n0 = blockIdx.x * 128;

    const __nv_bfloat16* __restrict__ Ah = (MODE == 0) ? g_in_h  : g_ctx_h;
    const __nv_bfloat16* __restrict__ Al = (MODE == 0) ? g_in_l  : g_ctx_l;
    const __nv_bfloat16* __restrict__ Bh = (MODE == 0) ? g_win_h : g_wout_h;
    const __nv_bfloat16* __restrict__ Bl = (MODE == 0) ? g_win_l : g_wout_l;

    auto issue_stage = [&](int k0, uint32_t sb) {
#pragma unroll
        for (int u = 0; u < 4; u++) {                 // A: 128 rows x 8 chunks
            const int s = u * 256 + tid;
            const int r = s >> 3, ck = s & 7;
            const size_t ga = (size_t)(m0 + r) * KDIM + k0 + ck * 8;
            const uint32_t off = (uint32_t)(r * RSH + ck * 8) * 2;
            cp16(sb + off,        Ah + ga);
            cp16(sb + G_AL + off, Al + ga);
        }
#pragma unroll
        for (int u = 0; u < 4; u++) {                 // B: 128 rows x 8 chunks
            const int s = u * 256 + tid;
            const int r = s >> 3, ck = s & 7;
            const size_t gb = (size_t)(n0 + r) * KDIM + k0 + ck * 8;
            const uint32_t off = (uint32_t)(r * RSH + ck * 8) * 2;
            cp16(sb + G_BH + off, Bh + gb);
            cp16(sb + G_BL + off, Bl + gb);
        }
        CP_COMMIT();
    };

    float acc[4][4][4];
#pragma unroll
    for (int mi = 0; mi < 4; mi++)
#pragma unroll
        for (int nj = 0; nj < 4; nj++)
#pragma unroll
            for (int q = 0; q < 4; q++) acc[mi][nj][q] = 0.f;

    const int lrow = lane & 15;
    const int lcol = (lane >> 4) << 3;

    // fragment double buffers: A 4 m-frags, B 2 p-frags (hi/lo each)
    uint32_t fah[2][4][4], fal[2][4][4], fbh[2][2][4], fbl[2][2][4];

    auto ldfrags = [&](uint32_t sb, int ks, int b) {
        const int kc = ks * 16 + lcol;
#pragma unroll
        for (int mi = 0; mi < 4; mi++) {
            const uint32_t ad = sb + ((wy * 64 + mi * 16 + lrow) * RSH + kc) * 2;
            ldsm_x4(fah[b][mi], ad);
            ldsm_x4(fal[b][mi], ad + G_AL);
        }
#pragma unroll
        for (int p = 0; p < 2; p++) {
            const uint32_t bd = sb + G_BH + ((wx * 32 + p * 16 + lrow) * RSH + kc) * 2;
            ldsm_x4(fbh[b][p], bd);
            ldsm_x4(fbl[b][p], bd + (G_BL - G_BH));
        }
    };
    auto docompute = [&](int b) {
#pragma unroll
        for (int mi = 0; mi < 4; mi++)
#pragma unroll
            for (int nj = 0; nj < 4; nj++) {
                const int p = nj >> 1, o = nj & 1;
                mma_bf16(acc[mi][nj], fah[b][mi][0], fah[b][mi][1], fah[b][mi][2], fah[b][mi][3],
                         fbh[b][p][o], fbh[b][p][o + 2]);
                mma_bf16(acc[mi][nj], fah[b][mi][0], fah[b][mi][1], fah[b][mi][2], fah[b][mi][3],
                         fbl[b][p][o], fbl[b][p][o + 2]);
                mma_bf16(acc[mi][nj], fal[b][mi][0], fal[b][mi][1], fal[b][mi][2], fal[b][mi][3],
                         fbh[b][p][o], fbh[b][p][o + 2]);
            }
    };

    issue_stage(0, sbase);

    const int NIT = KDIM / 64;   // 16
    for (int i = 0; i < NIT; i++) {
        CP_WAIT(0);
        __syncthreads();
        const uint32_t sb = sbase + (i & 1) * G_STAGE;
        ldfrags(sb, 0, 0);
        if (i + 1 < NIT)
            issue_stage((i + 1) * 64, sbase + ((i + 1) & 1) * G_STAGE);
#pragma unroll
        for (int ks = 0; ks < 4; ks++) {
            if (ks < 3) ldfrags(sb, ks + 1, (ks + 1) & 1);
            docompute(ks & 1);
        }
    }

    // ---- epilogue
#pragma unroll
    for (int mi = 0; mi < 4; mi++) {
        const int row0 = m0 + wy * 64 + mi * 16 + g;
        const int row1 = row0 + 8;
#pragma unroll
        for (int nj = 0; nj < 4; nj++) {
            const int col = n0 + wx * 32 + nj * 8 + 2 * t;
            if (MODE == 1) {
                *(float2*)&Cout[(size_t)row0 * CDIM + col] =
                    make_float2(acc[mi][nj][0], acc[mi][nj][1]);
                *(float2*)&Cout[(size_t)row1 * CDIM + col] =
                    make_float2(acc[mi][nj][2], acc[mi][nj][3]);
            } else {
                const int which = col >> 10;
                __nv_bfloat16* dh = (which == 0) ? g_qh : ((which == 1) ? g_kh : g_vh);
                __nv_bfloat16* dl = (which == 0) ? g_ql : ((which == 1) ? g_kl : g_vl);
                const int hh = (col & 1023) >> 6;
                const int dd = col & 63;
                uint32_t hi, lo;
                pack_split2(acc[mi][nj][0], acc[mi][nj][1], hi, lo);
                {
                    const int br = row0 >> 11, lr2 = row0 & 2047;
                    const size_t idx = (((size_t)(br * NHEAD + hh)) * LSEQ + lr2) * DHEAD + dd;
                    *(uint32_t*)(dh + idx) = hi;
                    *(uint32_t*)(dl + idx) = lo;
                }
                pack_split2(acc[mi][nj][2], acc[mi][nj][3], hi, lo);
                {
                    const int br = row1 >> 11, lr2 = row1 & 2047;
                    const size_t idx = (((size_t)(br * NHEAD + hh)) * LSEQ + lr2) * DHEAD + dd;
                    *(uint32_t*)(dh + idx) = hi;
                    *(uint32_t*)(dl + idx) = lo;
                }
            }
        }
    }
}

// ---------------------------------------------------------------------------
// HMMA causal flash attention, 2-stage cp.async K/V pipeline, 2 CTAs/SM.
// (R14 version: interleaved exp/PV, tied-best measured)
// Br=128, Bc=64, 256 threads (8 warps). grid: (B*H, L/128) qtile reversed.
// ---------------------------------------------------------------------------
#define ARS 72
#define AQ_L 18432
#define AKV0 36864
#define A_KL 9216
#define A_VH 18432
#define A_VL 27648
#define A_STAGE 36864
#define SMEM_ATTN (AKV0 + 2 * A_STAGE)    // 110592

__global__ __launch_bounds__(256, 2) void attn_hmma()
{
    extern __shared__ __align__(16) char dsa[];
    const uint32_t sbase = smem_u32(dsa);

    const int tid  = threadIdx.x;
    const int w    = tid >> 5;
    const int lane = tid & 31;
    const int g = lane >> 2;
    const int t = lane & 3;
    const int lrow = lane & 15;
    const int lcol = (lane >> 4) << 3;

    const int bh = blockIdx.x;
    const int qt = (int)gridDim.y - 1 - (int)blockIdx.y;
    const int qbase = qt * 128;

    const size_t hoff = (size_t)bh * LSEQ * DHEAD;
    const __nv_bfloat16* __restrict__ Qh = g_qh + hoff;
    const __nv_bfloat16* __restrict__ Ql = g_ql + hoff;
    const __nv_bfloat16* __restrict__ Kh = g_kh + hoff;
    const __nv_bfloat16* __restrict__ Kl = g_kl + hoff;
    const __nv_bfloat16* __restrict__ Vh = g_vh + hoff;
    const __nv_bfloat16* __restrict__ Vl = g_vl + hoff;

    const int nkt = 2 * qt + 2;

    auto issue_kv = [&](int kt, uint32_t sb) {
#pragma unroll
        for (int it = 0; it < 2; it++) {
            const int s = it * 256 + tid;
            const int r = s >> 3, ck = s & 7;
            const size_t go = (size_t)(kt * 64 + r) * DHEAD + ck * 8;
            const uint32_t off = (uint32_t)(r * ARS + ck * 8) * 2;
            cp16(sb + off,        Kh + go);
            cp16(sb + A_KL + off, Kl + go);
            cp16(sb + A_VH + off, Vh + go);
            cp16(sb + A_VL + off, Vl + go);
        }
        CP_COMMIT();
    };

#pragma unroll
    for (int it = 0; it < 4; it++) {
        const int s = it * 256 + tid;
        const int r = s >> 3, ck = s & 7;
        const size_t go = (size_t)(qbase + r) * DHEAD + ck * 8;
        const uint32_t off = (uint32_t)(r * ARS + ck * 8) * 2;
        cp16(sbase + off,        Qh + go);
        cp16(sbase + AQ_L + off, Ql + go);
    }
    CP_COMMIT();
    issue_kv(0, sbase + AKV0);

    CP_WAIT(0);
    __syncthreads();
    uint32_t qfh[4][4], qfl[4][4];
#pragma unroll
    for (int ks = 0; ks < 4; ks++) {
        const uint32_t ad = sbase + ((w * 16 + lrow) * ARS + ks * 16 + lcol) * 2;
        ldsm_x4(qfh[ks], ad);
        ldsm_x4(qfl[ks], ad + AQ_L);
    }

    float O[8][4];
#pragma unroll
    for (int j = 0; j < 8; j++)
#pragma unroll
        for (int q = 0; q < 4; q++) O[j][q] = 0.f;
    float m0 = -1e30f, m1 = -1e30f, l0 = 0.f, l1 = 0.f;
    const float scale = 0.125f;
    const int row0 = qbase + w * 16 + g;
    const int row1 = row0 + 8;

    for (int kt = 0; kt < nkt; kt++) {
        const int kbase = kt * 64;

        CP_WAIT(0);
        __syncthreads();
        if (kt + 1 < nkt)
            issue_kv(kt + 1, sbase + AKV0 + ((kt + 1) & 1) * A_STAGE);

        const uint32_t sb = sbase + AKV0 + (kt & 1) * A_STAGE;

        // ---- S = Q K^T (3-term split)
        float S[8][4];
#pragma unroll
        for (int j = 0; j < 8; j++)
#pragma unroll
            for (int q = 0; q < 4; q++) S[j][q] = 0.f;

#pragma unroll
        for (int ks = 0; ks < 4; ks++) {
#pragma unroll
            for (int p = 0; p < 4; p++) {
                uint32_t kh0[4], kl0[4];
                const uint32_t bd = sb + ((p * 16 + lrow) * ARS + ks * 16 + lcol) * 2;
                ldsm_x4(kh0, bd);
                ldsm_x4(kl0, bd + A_KL);
#pragma unroll
                for (int o = 0; o < 2; o++) {
                    const int j = 2 * p + o;
                    mma_bf16(S[j], qfh[ks][0], qfh[ks][1], qfh[ks][2], qfh[ks][3],
                             kh0[o], kh0[o + 2]);
                    mma_bf16(S[j], qfh[ks][0], qfh[ks][1], qfh[ks][2], qfh[ks][3],
                             kl0[o], kl0[o + 2]);
                    mma_bf16(S[j], qfl[ks][0], qfl[ks][1], qfl[ks][2], qfl[ks][3],
                             kh0[o], kh0[o + 2]);
                }
            }
        }

        if (kt >= nkt - 2) {
#pragma unroll
            for (int j = 0; j < 8; j++) {
                const int col = kbase + j * 8 + 2 * t;
                if (col > row0)     S[j][0] = -1e30f;
                if (col + 1 > row0) S[j][1] = -1e30f;
                if (col > row1)     S[j][2] = -1e30f;
                if (col + 1 > row1) S[j][3] = -1e30f;
            }
        }

        // ---- row max + rescale
        float mt0 = -1e30f, mt1 = -1e30f;
#pragma unroll
        for (int j = 0; j < 8; j++) {
            mt0 = fmaxf(mt0, fmaxf(S[j][0], S[j][1]));
            mt1 = fmaxf(mt1, fmaxf(S[j][2], S[j][3]));
        }
        mt0 = fmaxf(mt0, __shfl_xor_sync(0xffffffffu, mt0, 1));
        mt0 = fmaxf(mt0, __shfl_xor_sync(0xffffffffu, mt0, 2));
        mt1 = fmaxf(mt1, __shfl_xor_sync(0xffffffffu, mt1, 1));
        mt1 = fmaxf(mt1, __shfl_xor_sync(0xffffffffu, mt1, 2));
        const float mn0 = fmaxf(m0, mt0 * scale);
        const float mn1 = fmaxf(m1, mt1 * scale);
        const float a0 = __expf(m0 - mn0);
        const float a1 = __expf(m1 - mn1);
        m0 = mn0; m1 = mn1;
        l0 *= a0; l1 *= a1;
#pragma unroll
        for (int j = 0; j < 8; j++) {
            O[j][0] *= a0; O[j][1] *= a0;
            O[j][2] *= a1; O[j][3] *= a1;
        }

        // ---- interleaved exp (MUFU) -> pack -> PV MMAs (tensor)
        float rs0 = 0.f, rs1 = 0.f;
#pragma unroll
        for (int jj = 0; jj < 4; jj++) {
            const int j0 = 2 * jj, j1 = 2 * jj + 1;
            S[j0][0] = __expf(fmaf(S[j0][0], scale, -mn0));
            S[j0][1] = __expf(fmaf(S[j0][1], scale, -mn0));
            S[j0][2] = __expf(fmaf(S[j0][2], scale, -mn1));
            S[j0][3] = __expf(fmaf(S[j0][3], scale, -mn1));
            S[j1][0] = __expf(fmaf(S[j1][0], scale, -mn0));
            S[j1][1] = __expf(fmaf(S[j1][1], scale, -mn0));
            S[j1][2] = __expf(fmaf(S[j1][2], scale, -mn1));
            S[j1][3] = __expf(fmaf(S[j1][3], scale, -mn1));
            rs0 += S[j0][0] + S[j0][1] + S[j1][0] + S[j1][1];
            rs1 += S[j0][2] + S[j0][3] + S[j1][2] + S[j1][3];

            uint32_t ah[4], al[4];
            pack_split2(S[j0][0], S[j0][1], ah[0], al[0]);
            pack_split2(S[j0][2], S[j0][3], ah[1], al[1]);
            pack_split2(S[j1][0], S[j1][1], ah[2], al[2]);
            pack_split2(S[j1][2], S[j1][3], ah[3], al[3]);
#pragma unroll
            for (int p = 0; p < 4; p++) {
                uint32_t vh0[4], vl0[4];
                const uint32_t vd = sb + A_VH + ((jj * 16 + lrow) * ARS + p * 16 + lcol) * 2;
                ldsm_x4_t(vh0, vd);
                ldsm_x4_t(vl0, vd + (A_VL - A_VH));
#pragma unroll
                for (int o = 0; o < 2; o++) {
                    const int j2 = 2 * p + o;
                    mma_bf16(O[j2], ah[0], ah[1], ah[2], ah[3], vh0[2 * o], vh0[2 * o + 1]);
                    mma_bf16(O[j2], ah[0], ah[1], ah[2], ah[3], vl0[2 * o], vl0[2 * o + 1]);
                    mma_bf16(O[j2], al[0], al[1], al[2], al[3], vh0[2 * o], vh0[2 * o + 1]);
                }
            }
        }

        rs0 += __shfl_xor_sync(0xffffffffu, rs0, 1);
        rs0 += __shfl_xor_sync(0xffffffffu, rs0, 2);
        rs1 += __shfl_xor_sync(0xffffffffu, rs1, 1);
        rs1 += __shfl_xor_sync(0xffffffffu, rs1, 2);
        l0 += rs0;
        l1 += rs1;
    }

    const int b = bh >> 4;
    const int h = bh & 15;
    const float i0 = 1.f / l0;
    const float i1 = 1.f / l1;
#pragma unroll
    for (int j = 0; j < 8; j++) {
        const int col = h * DHEAD + j * 8 + 2 * t;
        uint32_t hi, lo;
        pack_split2(O[j][0] * i0, O[j][1] * i0, hi, lo);
        {
            const size_t idx = ((size_t)(b * LSEQ + row0)) * CDIM + col;
            *(uint32_t*)(g_ctx_h + idx) = hi;
            *(uint32_t*)(g_ctx_l + idx) = lo;
        }
        pack_split2(O[j][2] * i1, O[j][3] * i1, hi, lo);
        {
            const size_t idx = ((size_t)(b * LSEQ + row1)) * CDIM + col;
            *(uint32_t*)(g_ctx_h + idx) = hi;
            *(uint32_t*)(g_ctx_l + idx) = lo;
        }
    }
}

// ---------------------------------------------------------------------------
extern "C" void kernel_launch(void* const* d_in, const int* in_sizes, int n_in,
                              void* d_out, int out_size)
{
    const float* input = (const float*)d_in[0];
    const float* w_in  = (const float*)d_in[1];
    const float* w_out = (const float*)d_in[2];
    float* out = (float*)d_out;

    cudaFuncSetAttribute(gemm_hmma<0>, cudaFuncAttributeMaxDynamicSharedMemorySize, SMEM_GEMM);
    cudaFuncSetAttribute(gemm_hmma<1>, cudaFuncAttributeMaxDynamicSharedMemorySize, SMEM_GEMM);
    cudaFuncSetAttribute(attn_hmma,    cudaFuncAttributeMaxDynamicSharedMemorySize, SMEM_ATTN);

    cvt_kernel<<<(CVT_TOTAL + 511) / 512, 256>>>(input, w_in, w_out);

    gemm_hmma<0><<<dim3(3 * CDIM / 128, MROWS / 128), 256, SMEM_GEMM>>>(nullptr);
    attn_hmma<<<dim3(BATCH * NHEAD, LSEQ / 128), 256, SMEM_ATTN>>>();
    gemm_hmma<1><<<dim3(CDIM / 128, MROWS / 128), 256, SMEM_GEMM>>>(out);
}

// round 16
// speedup vs baseline: 1.1694x; 1.1694x over previous
#include <cuda_runtime.h>
#include <cuda_bf16.h>
#include <cuda_fp16.h>
#include <cstdint>

// ---------------------------------------------------------------------------
// Problem constants
// ---------------------------------------------------------------------------
#define BATCH 4
#define LSEQ  2048
#define CDIM  1024
#define NHEAD 16
#define DHEAD 64
#define MROWS (BATCH * LSEQ)   // 8192
#define KDIM  1024

// ---------------------------------------------------------------------------
// Device-global scratch (allocation-free per harness rules)
// ---------------------------------------------------------------------------
__device__ __nv_bfloat16 g_in_h [MROWS * KDIM];
__device__ __nv_bfloat16 g_in_l [MROWS * KDIM];
__device__ __nv_bfloat16 g_win_h[3 * CDIM * KDIM];
__device__ __nv_bfloat16 g_win_l[3 * CDIM * KDIM];
__device__ __half        g_wout [CDIM * KDIM];          // single fp16
__device__ __nv_bfloat16 g_qh[BATCH * NHEAD * LSEQ * DHEAD];
__device__ __nv_bfloat16 g_ql[BATCH * NHEAD * LSEQ * DHEAD];
__device__ __nv_bfloat16 g_kh[BATCH * NHEAD * LSEQ * DHEAD];
__device__ __nv_bfloat16 g_kl[BATCH * NHEAD * LSEQ * DHEAD];
__device__ __nv_bfloat16 g_vh[BATCH * NHEAD * LSEQ * DHEAD];
__device__ __nv_bfloat16 g_vl[BATCH * NHEAD * LSEQ * DHEAD];
__device__ __half        g_ctx_h[MROWS * CDIM];          // fp16 hi
__device__ __half        g_ctx_l[MROWS * CDIM];          // fp16 lo

// ---------------------------------------------------------------------------
// Baseline-PTX helpers (compute_103-safe: mma.sync, ldmatrix, cp.async)
// ---------------------------------------------------------------------------
__device__ __forceinline__ uint32_t smem_u32(const void* p) {
    uint32_t a;
    asm("{ .reg .u64 t; cvta.to.shared.u64 t, %1; cvt.u32.u64 %0, t; }"
        : "=r"(a) : "l"(p));
    return a;
}
__device__ __forceinline__ void ldsm_x4(uint32_t r[4], uint32_t addr) {
    asm volatile("ldmatrix.sync.aligned.m8n8.x4.shared.b16 {%0,%1,%2,%3}, [%4];"
                 : "=r"(r[0]), "=r"(r[1]), "=r"(r[2]), "=r"(r[3]) : "r"(addr));
}
__device__ __forceinline__ void ldsm_x4_t(uint32_t r[4], uint32_t addr) {
    asm volatile("ldmatrix.sync.aligned.m8n8.x4.trans.shared.b16 {%0,%1,%2,%3}, [%4];"
                 : "=r"(r[0]), "=r"(r[1]), "=r"(r[2]), "=r"(r[3]) : "r"(addr));
}
__device__ __forceinline__ void mma_bf16(float c[4],
                                         uint32_t a0, uint32_t a1, uint32_t a2, uint32_t a3,
                                         uint32_t b0, uint32_t b1) {
    asm volatile(
        "mma.sync.aligned.m16n8k16.row.col.f32.bf16.bf16.f32 "
        "{%0,%1,%2,%3}, {%4,%5,%6,%7}, {%8,%9}, {%0,%1,%2,%3};"
        : "+f"(c[0]), "+f"(c[1]), "+f"(c[2]), "+f"(c[3])
        : "r"(a0), "r"(a1), "r"(a2), "r"(a3), "r"(b0), "r"(b1));
}
__device__ __forceinline__ void mma_f16(float c[4],
                                        uint32_t a0, uint32_t a1, uint32_t a2, uint32_t a3,
                                        uint32_t b0, uint32_t b1) {
    asm volatile(
        "mma.sync.aligned.m16n8k16.row.col.f32.f16.f16.f32 "
        "{%0,%1,%2,%3}, {%4,%5,%6,%7}, {%8,%9}, {%0,%1,%2,%3};"
        : "+f"(c[0]), "+f"(c[1]), "+f"(c[2]), "+f"(c[3])
        : "r"(a0), "r"(a1), "r"(a2), "r"(a3), "r"(b0), "r"(b1));
}
__device__ __forceinline__ void cp16(uint32_t dst, const void* src) {
    asm volatile("cp.async.cg.shared.global [%0], [%1], 16;" :: "r"(dst), "l"(src));
}
#define CP_COMMIT() asm volatile("cp.async.commit_group;" ::: "memory")
#define CP_WAIT(N)  asm volatile("cp.async.wait_group %0;" :: "n"(N) : "memory")

__device__ __forceinline__ void split_bf16(float x, __nv_bfloat16& h, __nv_bfloat16& l) {
    h = __float2bfloat16(x);
    l = __float2bfloat16(x - __bfloat162float(h));
}
__device__ __forceinline__ void pack_split2(float x, float y, uint32_t& hi, uint32_t& lo) {
    __nv_bfloat162 h = __floats2bfloat162_rn(x, y);
    float2 hf = __bfloat1622float2(h);
    __nv_bfloat162 l = __floats2bfloat162_rn(x - hf.x, y - hf.y);
    hi = *(uint32_t*)&h;
    lo = *(uint32_t*)&l;
}
// fp16 variant for ctx
__device__ __forceinline__ void pack_split2_f16(float x, float y, uint32_t& hi, uint32_t& lo) {
    __half2 h = __floats2half2_rn(x, y);
    float2 hf = __half22float2(h);
    __half2 l = __floats2half2_rn(x - hf.x, y - hf.y);
    hi = *(uint32_t*)&h;
    lo = *(uint32_t*)&l;
}

// ---------------------------------------------------------------------------
// Conversions: input/w_in -> bf16 hi/lo; w_out -> single fp16.
// ---------------------------------------------------------------------------
#define CVT_N_IN   (MROWS * KDIM / 4)
#define CVT_N_WIN  (3 * CDIM * KDIM / 4)
#define CVT_N_WOUT (CDIM * KDIM / 4)
#define CVT_TOTAL  (CVT_N_IN + CVT_N_WIN + CVT_N_WOUT)

__device__ __forceinline__ void cvt_one(int i,
                                        const float* __restrict__ in,
                                        const float* __restrict__ w_in,
                                        const float* __restrict__ w_out)
{
    if (i < CVT_N_IN + CVT_N_WIN) {
        const float* src;
        __nv_bfloat16* hp;
        __nv_bfloat16* lp;
        int j;
        if (i < CVT_N_IN) { src = in;   hp = g_in_h;  lp = g_in_l;  j = i; }
        else              { src = w_in; hp = g_win_h; lp = g_win_l; j = i - CVT_N_IN; }
        float4 v = ((const float4*)src)[j];
        __nv_bfloat16 h0, h1, h2, h3, l0, l1, l2, l3;
        split_bf16(v.x, h0, l0); split_bf16(v.y, h1, l1);
        split_bf16(v.z, h2, l2); split_bf16(v.w, h3, l3);
        __nv_bfloat162 a, b;
        a.x = h0; a.y = h1; b.x = h2; b.y = h3;
        *(__nv_bfloat162*)(hp + 4 * (size_t)j)     = a;
        *(__nv_bfloat162*)(hp + 4 * (size_t)j + 2) = b;
        a.x = l0; a.y = l1; b.x = l2; b.y = l3;
        *(__nv_bfloat162*)(lp + 4 * (size_t)j)     = a;
        *(__nv_bfloat162*)(lp + 4 * (size_t)j + 2) = b;
    } else {
        const int j = i - CVT_N_IN - CVT_N_WIN;
        float4 v = ((const float4*)w_out)[j];
        __half2 a = __floats2half2_rn(v.x, v.y);
        __half2 b = __floats2half2_rn(v.z, v.w);
        *(__half2*)(g_wout + 4 * (size_t)j)     = a;
        *(__half2*)(g_wout + 4 * (size_t)j + 2) = b;
    }
}

__global__ __launch_bounds__(256) void cvt_kernel(const float* __restrict__ in,
                                                  const float* __restrict__ w_in,
                                                  const float* __restrict__ w_out)
{
    const int base = blockIdx.x * 512 + threadIdx.x;
    if (base < CVT_TOTAL) cvt_one(base, in, w_in, w_out);
    if (base + 256 < CVT_TOTAL) cvt_one(base + 256, in, w_in, w_out);
}

// ---------------------------------------------------------------------------
// GEMM1: HMMA split-bf16 NT GEMM (R9 exact). BK=64, 2-stage cp.async,
// 2 CTAs/SM, BM=64, BN=128, 256 threads, warp tile 32x32, frag double-buffer.
// Per-stage (bytes): AH 0, AL 9216, BH 18432, BL 36864; stage 55296.
// ---------------------------------------------------------------------------
#define RSH 72
#define G_AL 9216
#define G_BH 18432
#define G_BL 36864
#define G_STAGE 55296
#define SMEM_GEMM (2 * G_STAGE)           // 110592

__global__ __launch_bounds__(256, 2) void gemm_qkv()
{
    extern __shared__ __align__(16) char dsm[];
    const uint32_t sbase = smem_u32(dsm);

    const int tid  = threadIdx.x;
    const int wid  = tid >> 5;
    const int lane = tid & 31;
    const int wy = wid >> 2;
    const int wx = wid & 3;
    const int g = lane >> 2;
    const int t = lane & 3;
    const int m0 = blockIdx.y * 64;
    const int n0 = blockIdx.x * 128;

    const __nv_bfloat16* __restrict__ Ah = g_in_h;
    const __nv_bfloat16* __restrict__ Al = g_in_l;
    const __nv_bfloat16* __restrict__ Bh = g_win_h;
    const __nv_bfloat16* __restrict__ Bl = g_win_l;

    auto issue_stage = [&](int k0, uint32_t sb) {
#pragma unroll
        for (int u = 0; u < 2; u++) {
            const int s = u * 256 + tid;
            const int r = s >> 3, ck = s & 7;
            const size_t ga = (size_t)(m0 + r) * KDIM + k0 + ck * 8;
            const uint32_t off = (uint32_t)(r * RSH + ck * 8) * 2;
            cp16(sb + off,        Ah + ga);
            cp16(sb + G_AL + off, Al + ga);
        }
#pragma unroll
        for (int u = 0; u < 4; u++) {
            const int s = u * 256 + tid;
            const int r = s >> 3, ck = s & 7;
            const size_t gb = (size_t)(n0 + r) * KDIM + k0 + ck * 8;
            const uint32_t off = (uint32_t)(r * RSH + ck * 8) * 2;
            cp16(sb + G_BH + off, Bh + gb);
            cp16(sb + G_BL + off, Bl + gb);
        }
        CP_COMMIT();
    };

    float acc[2][4][4];
#pragma unroll
    for (int mi = 0; mi < 2; mi++)
#pragma unroll
        for (int nj = 0; nj < 4; nj++)
#pragma unroll
            for (int q = 0; q < 4; q++) acc[mi][nj][q] = 0.f;

    const int lrow = lane & 15;
    const int lcol = (lane >> 4) << 3;

    uint32_t fah[2][2][4], fal[2][2][4], fbh[2][2][4], fbl[2][2][4];

    auto ldfrags = [&](uint32_t sb, int ks, int b) {
        const int kc = ks * 16 + lcol;
#pragma unroll
        for (int mi = 0; mi < 2; mi++) {
            const uint32_t ad = sb + ((wy * 32 + mi * 16 + lrow) * RSH + kc) * 2;
            ldsm_x4(fah[b][mi], ad);
            ldsm_x4(fal[b][mi], ad + G_AL);
        }
#pragma unroll
        for (int p = 0; p < 2; p++) {
            const uint32_t bd = sb + G_BH + ((wx * 32 + p * 16 + lrow) * RSH + kc) * 2;
            ldsm_x4(fbh[b][p], bd);
            ldsm_x4(fbl[b][p], bd + (G_BL - G_BH));
        }
    };
    auto docompute = [&](int b) {
#pragma unroll
        for (int mi = 0; mi < 2; mi++)
#pragma unroll
            for (int nj = 0; nj < 4; nj++) {
                const int p = nj >> 1, o = nj & 1;
                mma_bf16(acc[mi][nj], fah[b][mi][0], fah[b][mi][1], fah[b][mi][2], fah[b][mi][3],
                         fbh[b][p][o], fbh[b][p][o + 2]);
                mma_bf16(acc[mi][nj], fah[b][mi][0], fah[b][mi][1], fah[b][mi][2], fah[b][mi][3],
                         fbl[b][p][o], fbl[b][p][o + 2]);
                mma_bf16(acc[mi][nj], fal[b][mi][0], fal[b][mi][1], fal[b][mi][2], fal[b][mi][3],
                         fbh[b][p][o], fbh[b][p][o + 2]);
            }
    };

    issue_stage(0, sbase);

    const int NIT = KDIM / 64;   // 16
    for (int i = 0; i < NIT; i++) {
        CP_WAIT(0);
        __syncthreads();
        const uint32_t sb = sbase + (i & 1) * G_STAGE;
        ldfrags(sb, 0, 0);
        if (i + 1 < NIT)
            issue_stage((i + 1) * 64, sbase + ((i + 1) & 1) * G_STAGE);
#pragma unroll
        for (int ks = 0; ks < 4; ks++) {
            if (ks < 3) ldfrags(sb, ks + 1, (ks + 1) & 1);
            docompute(ks & 1);
        }
    }

    // epilogue: scatter q/k/v bf16 hi/lo
#pragma unroll
    for (int mi = 0; mi < 2; mi++) {
        const int row0 = m0 + wy * 32 + mi * 16 + g;
        const int row1 = row0 + 8;
#pragma unroll
        for (int nj = 0; nj < 4; nj++) {
            const int col = n0 + wx * 32 + nj * 8 + 2 * t;
            const int which = col >> 10;
            __nv_bfloat16* dh = (which == 0) ? g_qh : ((which == 1) ? g_kh : g_vh);
            __nv_bfloat16* dl = (which == 0) ? g_ql : ((which == 1) ? g_kl : g_vl);
            const int hh = (col & 1023) >> 6;
            const int dd = col & 63;
            uint32_t hi, lo;
            pack_split2(acc[mi][nj][0], acc[mi][nj][1], hi, lo);
            {
                const int br = row0 >> 11, lr2 = row0 & 2047;
                const size_t idx = (((size_t)(br * NHEAD + hh)) * LSEQ + lr2) * DHEAD + dd;
                *(uint32_t*)(dh + idx) = hi;
                *(uint32_t*)(dl + idx) = lo;
            }
            pack_split2(acc[mi][nj][2], acc[mi][nj][3], hi, lo);
            {
                const int br = row1 >> 11, lr2 = row1 & 2047;
                const size_t idx = (((size_t)(br * NHEAD + hh)) * LSEQ + lr2) * DHEAD + dd;
                *(uint32_t*)(dh + idx) = hi;
                *(uint32_t*)(dl + idx) = lo;
            }
        }
    }
}

// ---------------------------------------------------------------------------
// GEMM2: fp16 2-term NT GEMM. A = ctx (fp16 hi/lo), B = w_out (single fp16).
// D = Ah*B + Al*B. BK=64, 2-stage, 2 CTAs/SM, BM=64, BN=128, warp 32x32.
// Per-stage (bytes): AH 0, AL 9216, B 18432; stage 36864.
// ---------------------------------------------------------------------------
#define G2_AL 9216
#define G2_B  18432
#define G2_STAGE 36864
#define SMEM_GEMM2 (2 * G2_STAGE)         // 73728

__global__ __launch_bounds__(256, 2) void gemm_out(float* __restrict__ Cout)
{
    extern __shared__ __align__(16) char dsm[];
    const uint32_t sbase = smem_u32(dsm);

    const int tid  = threadIdx.x;
    const int wid  = tid >> 5;
    const int lane = tid & 31;
    const int wy = wid >> 2;
    const int wx = wid & 3;
    const int g = lane >> 2;
    const int t = lane & 3;
    const int m0 = blockIdx.y * 64;
    const int n0 = blockIdx.x * 128;

    const __half* __restrict__ Ah = g_ctx_h;
    const __half* __restrict__ Al = g_ctx_l;
    const __half* __restrict__ B  = g_wout;

    auto issue_stage = [&](int k0, uint32_t sb) {
#pragma unroll
        for (int u = 0; u < 2; u++) {                 // A: 64 rows x 8 chunks
            const int s = u * 256 + tid;
            const int r = s >> 3, ck = s & 7;
            const size_t ga = (size_t)(m0 + r) * KDIM + k0 + ck * 8;
            const uint32_t off = (uint32_t)(r * RSH + ck * 8) * 2;
            cp16(sb + off,         Ah + ga);
            cp16(sb + G2_AL + off, Al + ga);
        }
#pragma unroll
        for (int u = 0; u < 4; u++) {                 // B: 128 rows x 8 chunks
            const int s = u * 256 + tid;
            const int r = s >> 3, ck = s & 7;
            const size_t gb = (size_t)(n0 + r) * KDIM + k0 + ck * 8;
            const uint32_t off = (uint32_t)(r * RSH + ck * 8) * 2;
            cp16(sb + G2_B + off, B + gb);
        }
        CP_COMMIT();
    };

    float acc[2][4][4];
#pragma unroll
    for (int mi = 0; mi < 2; mi++)
#pragma unroll
        for (int nj = 0; nj < 4; nj++)
#pragma unroll
            for (int q = 0; q < 4; q++) acc[mi][nj][q] = 0.f;

    const int lrow = lane & 15;
    const int lcol = (lane >> 4) << 3;

    uint32_t fah[2][2][4], fal[2][2][4], fb[2][2][4];

    auto ldfrags = [&](uint32_t sb, int ks, int b) {
        const int kc = ks * 16 + lcol;
#pragma unroll
        for (int mi = 0; mi < 2; mi++) {
            const uint32_t ad = sb + ((wy * 32 + mi * 16 + lrow) * RSH + kc) * 2;
            ldsm_x4(fah[b][mi], ad);
            ldsm_x4(fal[b][mi], ad + G2_AL);
        }
#pragma unroll
        for (int p = 0; p < 2; p++) {
            const uint32_t bd = sb + G2_B + ((wx * 32 + p * 16 + lrow) * RSH + kc) * 2;
            ldsm_x4(fb[b][p], bd);
        }
    };
    auto docompute = [&](int b) {
#pragma unroll
        for (int mi = 0; mi < 2; mi++)
#pragma unroll
            for (int nj = 0; nj < 4; nj++) {
                const int p = nj >> 1, o = nj & 1;
                mma_f16(acc[mi][nj], fah[b][mi][0], fah[b][mi][1], fah[b][mi][2], fah[b][mi][3],
                        fb[b][p][o], fb[b][p][o + 2]);
                mma_f16(acc[mi][nj], fal[b][mi][0], fal[b][mi][1], fal[b][mi][2], fal[b][mi][3],
                        fb[b][p][o], fb[b][p][o + 2]);
            }
    };

    issue_stage(0, sbase);

    const int NIT = KDIM / 64;   // 16
    for (int i = 0; i < NIT; i++) {
        CP_WAIT(0);
        __syncthreads();
        const uint32_t sb = sbase + (i & 1) * G2_STAGE;
        ldfrags(sb, 0, 0);
        if (i + 1 < NIT)
            issue_stage((i + 1) * 64, sbase + ((i + 1) & 1) * G2_STAGE);
#pragma unroll
        for (int ks = 0; ks < 4; ks++) {
            if (ks < 3) ldfrags(sb, ks + 1, (ks + 1) & 1);
            docompute(ks & 1);
        }
    }

    // epilogue: fp32 row-major output
#pragma unroll
    for (int mi = 0; mi < 2; mi++) {
        const int row0 = m0 + wy * 32 + mi * 16 + g;
        const int row1 = row0 + 8;
#pragma unroll
        for (int nj = 0; nj < 4; nj++) {
            const int col = n0 + wx * 32 + nj * 8 + 2 * t;
            *(float2*)&Cout[(size_t)row0 * CDIM + col] =
                make_float2(acc[mi][nj][0], acc[mi][nj][1]);
            *(float2*)&Cout[(size_t)row1 * CDIM + col] =
                make_float2(acc[mi][nj][2], acc[mi][nj][3]);
        }
    }
}

// ---------------------------------------------------------------------------
// HMMA causal flash attention, 2-stage cp.async K/V pipeline, 2 CTAs/SM.
// (R9's best-measured body; ctx epilogue now writes fp16 hi/lo)
// Br=128, Bc=64, 256 threads (8 warps). grid: (B*H, L/128) qtile reversed.
// ---------------------------------------------------------------------------
#define ARS 72
#define AQ_L 18432
#define AKV0 36864
#define A_KL 9216
#define A_VH 18432
#define A_VL 27648
#define A_STAGE 36864
#define SMEM_ATTN (AKV0 + 2 * A_STAGE)    // 110592

__global__ __launch_bounds__(256, 2) void attn_hmma()
{
    extern __shared__ __align__(16) char dsa[];
    const uint32_t sbase = smem_u32(dsa);

    const int tid  = threadIdx.x;
    const int w    = tid >> 5;
    const int lane = tid & 31;
    const int g = lane >> 2;
    const int t = lane & 3;
    const int lrow = lane & 15;
    const int lcol = (lane >> 4) << 3;

    const int bh = blockIdx.x;
    const int qt = (int)gridDim.y - 1 - (int)blockIdx.y;
    const int qbase = qt * 128;

    const size_t hoff = (size_t)bh * LSEQ * DHEAD;
    const __nv_bfloat16* __restrict__ Qh = g_qh + hoff;
    const __nv_bfloat16* __restrict__ Ql = g_ql + hoff;
    const __nv_bfloat16* __restrict__ Kh = g_kh + hoff;
    const __nv_bfloat16* __restrict__ Kl = g_kl + hoff;
    const __nv_bfloat16* __restrict__ Vh = g_vh + hoff;
    const __nv_bfloat16* __restrict__ Vl = g_vl + hoff;

    const int nkt = 2 * qt + 2;

    auto issue_kv = [&](int kt, uint32_t sb) {
#pragma unroll
        for (int it = 0; it < 2; it++) {
            const int s = it * 256 + tid;
            const int r = s >> 3, ck = s & 7;
            const size_t go = (size_t)(kt * 64 + r) * DHEAD + ck * 8;
            const uint32_t off = (uint32_t)(r * ARS + ck * 8) * 2;
            cp16(sb + off,        Kh + go);
            cp16(sb + A_KL + off, Kl + go);
            cp16(sb + A_VH + off, Vh + go);
            cp16(sb + A_VL + off, Vl + go);
        }
        CP_COMMIT();
    };

#pragma unroll
    for (int it = 0; it < 4; it++) {
        const int s = it * 256 + tid;
        const int r = s >> 3, ck = s & 7;
        const size_t go = (size_t)(qbase + r) * DHEAD + ck * 8;
        const uint32_t off = (uint32_t)(r * ARS + ck * 8) * 2;
        cp16(sbase + off,        Qh + go);
        cp16(sbase + AQ_L + off, Ql + go);
    }
    CP_COMMIT();
    issue_kv(0, sbase + AKV0);

    CP_WAIT(0);
    __syncthreads();
    uint32_t qfh[4][4], qfl[4][4];
#pragma unroll
    for (int ks = 0; ks < 4; ks++) {
        const uint32_t ad = sbase + ((w * 16 + lrow) * ARS + ks * 16 + lcol) * 2;
        ldsm_x4(qfh[ks], ad);
        ldsm_x4(qfl[ks], ad + AQ_L);
    }

    float O[8][4];
#pragma unroll
    for (int j = 0; j < 8; j++)
#pragma unroll
        for (int q = 0; q < 4; q++) O[j][q] = 0.f;
    float m0 = -1e30f, m1 = -1e30f, l0 = 0.f, l1 = 0.f;
    const float scale = 0.125f;
    const int row0 = qbase + w * 16 + g;
    const int row1 = row0 + 8;

    for (int kt = 0; kt < nkt; kt++) {
        const int kbase = kt * 64;

        CP_WAIT(0);
        __syncthreads();
        if (kt + 1 < nkt)
            issue_kv(kt + 1, sbase + AKV0 + ((kt + 1) & 1) * A_STAGE);

        const uint32_t sb = sbase + AKV0 + (kt & 1) * A_STAGE;

        float S[8][4];
#pragma unroll
        for (int j = 0; j < 8; j++)
#pragma unroll
            for (int q = 0; q < 4; q++) S[j][q] = 0.f;

#pragma unroll
        for (int ks = 0; ks < 4; ks++) {
#pragma unroll
            for (int p = 0; p < 4; p++) {
                uint32_t kh0[4], kl0[4];
                const uint32_t bd = sb + ((p * 16 + lrow) * ARS + ks * 16 + lcol) * 2;
                ldsm_x4(kh0, bd);
                ldsm_x4(kl0, bd + A_KL);
#pragma unroll
                for (int o = 0; o < 2; o++) {
                    const int j = 2 * p + o;
                    mma_bf16(S[j], qfh[ks][0], qfh[ks][1], qfh[ks][2], qfh[ks][3],
                             kh0[o], kh0[o + 2]);
                    mma_bf16(S[j], qfh[ks][0], qfh[ks][1], qfh[ks][2], qfh[ks][3],
                             kl0[o], kl0[o + 2]);
                    mma_bf16(S[j], qfl[ks][0], qfl[ks][1], qfl[ks][2], qfl[ks][3],
                             kh0[o], kh0[o + 2]);
                }
            }
        }

        if (kt >= nkt - 2) {
#pragma unroll
            for (int j = 0; j < 8; j++) {
                const int col = kbase + j * 8 + 2 * t;
                if (col > row0)     S[j][0] = -1e30f;
                if (col + 1 > row0) S[j][1] = -1e30f;
                if (col > row1)     S[j][2] = -1e30f;
                if (col + 1 > row1) S[j][3] = -1e30f;
            }
        }

        float mt0 = -1e30f, mt1 = -1e30f;
#pragma unroll
        for (int j = 0; j < 8; j++) {
            mt0 = fmaxf(mt0, fmaxf(S[j][0], S[j][1]));
            mt1 = fmaxf(mt1, fmaxf(S[j][2], S[j][3]));
        }
        mt0 = fmaxf(mt0, __shfl_xor_sync(0xffffffffu, mt0, 1));
        mt0 = fmaxf(mt0, __shfl_xor_sync(0xffffffffu, mt0, 2));
        mt1 = fmaxf(mt1, __shfl_xor_sync(0xffffffffu, mt1, 1));
        mt1 = fmaxf(mt1, __shfl_xor_sync(0xffffffffu, mt1, 2));
        const float mn0 = fmaxf(m0, mt0 * scale);
        const float mn1 = fmaxf(m1, mt1 * scale);
        const float a0 = __expf(m0 - mn0);
        const float a1 = __expf(m1 - mn1);
        m0 = mn0; m1 = mn1;

        float rs0 = 0.f, rs1 = 0.f;
#pragma unroll
        for (int j = 0; j < 8; j++) {
            S[j][0] = __expf(fmaf(S[j][0], scale, -mn0));
            S[j][1] = __expf(fmaf(S[j][1], scale, -mn0));
            S[j][2] = __expf(fmaf(S[j][2], scale, -mn1));
            S[j][3] = __expf(fmaf(S[j][3], scale, -mn1));
            rs0 += S[j][0] + S[j][1];
            rs1 += S[j][2] + S[j][3];
        }
        rs0 += __shfl_xor_sync(0xffffffffu, rs0, 1);
        rs0 += __shfl_xor_sync(0xffffffffu, rs0, 2);
        rs1 += __shfl_xor_sync(0xffffffffu, rs1, 1);
        rs1 += __shfl_xor_sync(0xffffffffu, rs1, 2);
        l0 = l0 * a0 + rs0;
        l1 = l1 * a1 + rs1;
#pragma unroll
        for (int j = 0; j < 8; j++) {
            O[j][0] *= a0; O[j][1] *= a0;
            O[j][2] *= a1; O[j][3] *= a1;
        }

#pragma unroll
        for (int jj = 0; jj < 4; jj++) {
            uint32_t ah[4], al[4];
            pack_split2(S[2 * jj][0],     S[2 * jj][1],     ah[0], al[0]);
            pack_split2(S[2 * jj][2],     S[2 * jj][3],     ah[1], al[1]);
            pack_split2(S[2 * jj + 1][0], S[2 * jj + 1][1], ah[2], al[2]);
            pack_split2(S[2 * jj + 1][2], S[2 * jj + 1][3], ah[3], al[3]);
#pragma unroll
            for (int p = 0; p < 4; p++) {
                uint32_t vh0[4], vl0[4];
                const uint32_t vd = sb + A_VH + ((jj * 16 + lrow) * ARS + p * 16 + lcol) * 2;
                ldsm_x4_t(vh0, vd);
                ldsm_x4_t(vl0, vd + (A_VL - A_VH));
#pragma unroll
                for (int o = 0; o < 2; o++) {
                    const int j2 = 2 * p + o;
                    mma_bf16(O[j2], ah[0], ah[1], ah[2], ah[3], vh0[2 * o], vh0[2 * o + 1]);
                    mma_bf16(O[j2], ah[0], ah[1], ah[2], ah[3], vl0[2 * o], vl0[2 * o + 1]);
                    mma_bf16(O[j2], al[0], al[1], al[2], al[3], vh0[2 * o], vh0[2 * o + 1]);
                }
            }
        }
    }

    // finalize + write ctx hi/lo fp16 [b*l][h*64+d]
    const int b = bh >> 4;
    const int h = bh & 15;
    const float i0 = 1.f / l0;
    const float i1 = 1.f / l1;
#pragma unroll
    for (int j = 0; j < 8; j++) {
        const int col = h * DHEAD + j * 8 + 2 * t;
        uint32_t hi, lo;
        pack_split2_f16(O[j][0] * i0, O[j][1] * i0, hi, lo);
        {
            const size_t idx = ((size_t)(b * LSEQ + row0)) * CDIM + col;
            *(uint32_t*)(g_ctx_h + idx) = hi;
            *(uint32_t*)(g_ctx_l + idx) = lo;
        }
        pack_split2_f16(O[j][2] * i1, O[j][3] * i1, hi, lo);
        {
            const size_t idx = ((size_t)(b * LSEQ + row1)) * CDIM + col;
            *(uint32_t*)(g_ctx_h + idx) = hi;
            *(uint32_t*)(g_ctx_l + idx) = lo;
        }
    }
}

// ---------------------------------------------------------------------------
extern "C" void kernel_launch(void* const* d_in, const int* in_sizes, int n_in,
                              void* d_out, int out_size)
{
    const float* input = (const float*)d_in[0];
    const float* w_in  = (const float*)d_in[1];
    const float* w_out = (const float*)d_in[2];
    float* out = (float*)d_out;

    cudaFuncSetAttribute(gemm_qkv, cudaFuncAttributeMaxDynamicSharedMemorySize, SMEM_GEMM);
    cudaFuncSetAttribute(gemm_out, cudaFuncAttributeMaxDynamicSharedMemorySize, SMEM_GEMM2);
    cudaFuncSetAttribute(attn_hmma, cudaFuncAttributeMaxDynamicSharedMemorySize, SMEM_ATTN);

    cvt_kernel<<<(CVT_TOTAL + 511) / 512, 256>>>(input, w_in, w_out);

    gemm_qkv<<<dim3(3 * CDIM / 128, MROWS / 64), 256, SMEM_GEMM>>>();
    attn_hmma<<<dim3(BATCH * NHEAD, LSEQ / 128), 256, SMEM_ATTN>>>();
    gemm_out<<<dim3(CDIM / 128, MROWS / 64), 256, SMEM_GEMM2>>>(out);
}

// round 17
// speedup vs baseline: 1.3827x; 1.1824x over previous
#include <cuda_runtime.h>
#include <cuda_bf16.h>
#include <cuda_fp16.h>
#include <cstdint>

// ---------------------------------------------------------------------------
// Problem constants
// ---------------------------------------------------------------------------
#define BATCH 4
#define LSEQ  2048
#define CDIM  1024
#define NHEAD 16
#define DHEAD 64
#define MROWS (BATCH * LSEQ)   // 8192
#define KDIM  1024

// ---------------------------------------------------------------------------
// Device-global scratch (allocation-free per harness rules)
// ---------------------------------------------------------------------------
__device__ __half        g_in_fh[MROWS * KDIM];          // input fp16 hi
__device__ __half        g_in_fl[MROWS * KDIM];          // input fp16 lo
__device__ __half        g_win_f[3 * CDIM * KDIM];       // w_in single fp16
__device__ __half        g_wout [CDIM * KDIM];           // w_out single fp16
__device__ __nv_bfloat16 g_qh[BATCH * NHEAD * LSEQ * DHEAD];
__device__ __nv_bfloat16 g_ql[BATCH * NHEAD * LSEQ * DHEAD];
__device__ __nv_bfloat16 g_kh[BATCH * NHEAD * LSEQ * DHEAD];
__device__ __nv_bfloat16 g_kl[BATCH * NHEAD * LSEQ * DHEAD];
__device__ __nv_bfloat16 g_vh[BATCH * NHEAD * LSEQ * DHEAD];
__device__ __nv_bfloat16 g_vl[BATCH * NHEAD * LSEQ * DHEAD];
__device__ __half        g_ctx_h[MROWS * CDIM];          // ctx fp16 hi
__device__ __half        g_ctx_l[MROWS * CDIM];          // ctx fp16 lo

// ---------------------------------------------------------------------------
// Baseline-PTX helpers (compute_103-safe: mma.sync, ldmatrix, cp.async)
// ---------------------------------------------------------------------------
__device__ __forceinline__ uint32_t smem_u32(const void* p) {
    uint32_t a;
    asm("{ .reg .u64 t; cvta.to.shared.u64 t, %1; cvt.u32.u64 %0, t; }"
        : "=r"(a) : "l"(p));
    return a;
}
__device__ __forceinline__ void ldsm_x4(uint32_t r[4], uint32_t addr) {
    asm volatile("ldmatrix.sync.aligned.m8n8.x4.shared.b16 {%0,%1,%2,%3}, [%4];"
                 : "=r"(r[0]), "=r"(r[1]), "=r"(r[2]), "=r"(r[3]) : "r"(addr));
}
__device__ __forceinline__ void ldsm_x4_t(uint32_t r[4], uint32_t addr) {
    asm volatile("ldmatrix.sync.aligned.m8n8.x4.trans.shared.b16 {%0,%1,%2,%3}, [%4];"
                 : "=r"(r[0]), "=r"(r[1]), "=r"(r[2]), "=r"(r[3]) : "r"(addr));
}
__device__ __forceinline__ void mma_bf16(float c[4],
                                         uint32_t a0, uint32_t a1, uint32_t a2, uint32_t a3,
                                         uint32_t b0, uint32_t b1) {
    asm volatile(
        "mma.sync.aligned.m16n8k16.row.col.f32.bf16.bf16.f32 "
        "{%0,%1,%2,%3}, {%4,%5,%6,%7}, {%8,%9}, {%0,%1,%2,%3};"
        : "+f"(c[0]), "+f"(c[1]), "+f"(c[2]), "+f"(c[3])
        : "r"(a0), "r"(a1), "r"(a2), "r"(a3), "r"(b0), "r"(b1));
}
__device__ __forceinline__ void mma_f16(float c[4],
                                        uint32_t a0, uint32_t a1, uint32_t a2, uint32_t a3,
                                        uint32_t b0, uint32_t b1) {
    asm volatile(
        "mma.sync.aligned.m16n8k16.row.col.f32.f16.f16.f32 "
        "{%0,%1,%2,%3}, {%4,%5,%6,%7}, {%8,%9}, {%0,%1,%2,%3};"
        : "+f"(c[0]), "+f"(c[1]), "+f"(c[2]), "+f"(c[3])
        : "r"(a0), "r"(a1), "r"(a2), "r"(a3), "r"(b0), "r"(b1));
}
__device__ __forceinline__ void cp16(uint32_t dst, const void* src) {
    asm volatile("cp.async.cg.shared.global [%0], [%1], 16;" :: "r"(dst), "l"(src));
}
#define CP_COMMIT() asm volatile("cp.async.commit_group;" ::: "memory")
#define CP_WAIT(N)  asm volatile("cp.async.wait_group %0;" :: "n"(N) : "memory")

__device__ __forceinline__ void pack_split2(float x, float y, uint32_t& hi, uint32_t& lo) {
    __nv_bfloat162 h = __floats2bfloat162_rn(x, y);
    float2 hf = __bfloat1622float2(h);
    __nv_bfloat162 l = __floats2bfloat162_rn(x - hf.x, y - hf.y);
    hi = *(uint32_t*)&h;
    lo = *(uint32_t*)&l;
}
__device__ __forceinline__ void pack_split2_f16(float x, float y, uint32_t& hi, uint32_t& lo) {
    __half2 h = __floats2half2_rn(x, y);
    float2 hf = __half22float2(h);
    __half2 l = __floats2half2_rn(x - hf.x, y - hf.y);
    hi = *(uint32_t*)&h;
    lo = *(uint32_t*)&l;
}

// ---------------------------------------------------------------------------
// Conversions: input -> fp16 hi/lo; w_in, w_out -> single fp16.
// ---------------------------------------------------------------------------
#define CVT_N_IN   (MROWS * KDIM / 4)
#define CVT_N_WIN  (3 * CDIM * KDIM / 4)
#define CVT_N_WOUT (CDIM * KDIM / 4)
#define CVT_TOTAL  (CVT_N_IN + CVT_N_WIN + CVT_N_WOUT)

__device__ __forceinline__ void cvt_one(int i,
                                        const float* __restrict__ in,
                                        const float* __restrict__ w_in,
                                        const float* __restrict__ w_out)
{
    if (i < CVT_N_IN) {
        float4 v = ((const float4*)in)[i];
        __half2 h0 = __floats2half2_rn(v.x, v.y);
        __half2 h1 = __floats2half2_rn(v.z, v.w);
        float2 f0 = __half22float2(h0);
        float2 f1 = __half22float2(h1);
        __half2 l0 = __floats2half2_rn(v.x - f0.x, v.y - f0.y);
        __half2 l1 = __floats2half2_rn(v.z - f1.x, v.w - f1.y);
        *(__half2*)(g_in_fh + 4 * (size_t)i)     = h0;
        *(__half2*)(g_in_fh + 4 * (size_t)i + 2) = h1;
        *(__half2*)(g_in_fl + 4 * (size_t)i)     = l0;
        *(__half2*)(g_in_fl + 4 * (size_t)i + 2) = l1;
    } else if (i < CVT_N_IN + CVT_N_WIN) {
        const int j = i - CVT_N_IN;
        float4 v = ((const float4*)w_in)[j];
        *(__half2*)(g_win_f + 4 * (size_t)j)     = __floats2half2_rn(v.x, v.y);
        *(__half2*)(g_win_f + 4 * (size_t)j + 2) = __floats2half2_rn(v.z, v.w);
    } else {
        const int j = i - CVT_N_IN - CVT_N_WIN;
        float4 v = ((const float4*)w_out)[j];
        *(__half2*)(g_wout + 4 * (size_t)j)     = __floats2half2_rn(v.x, v.y);
        *(__half2*)(g_wout + 4 * (size_t)j + 2) = __floats2half2_rn(v.z, v.w);
    }
}

__global__ __launch_bounds__(256) void cvt_kernel(const float* __restrict__ in,
                                                  const float* __restrict__ w_in,
                                                  const float* __restrict__ w_out)
{
    const int base = blockIdx.x * 512 + threadIdx.x;
    if (base < CVT_TOTAL) cvt_one(base, in, w_in, w_out);
    if (base + 256 < CVT_TOTAL) cvt_one(base + 256, in, w_in, w_out);
}

// ---------------------------------------------------------------------------
// fp16 2-term NT GEMM: D = Ah*B + Al*B (A fp16 hi/lo, B single fp16).
// BK=64, 2-stage cp.async, 2 CTAs/SM, BM=64, BN=128, 256 threads,
// warp tile 32x32, register double-buffered fragments.
// Per-stage (bytes): AH 0, AL 9216, B 18432; stage 36864.
// MODE 0: A=input, B=w_in, scatter q/k/v bf16 hi/lo.
// MODE 1: A=ctx,   B=w_out, fp32 row-major out.
// ---------------------------------------------------------------------------
#define RSH 72
#define G2_AL 9216
#define G2_B  18432
#define G2_STAGE 36864
#define SMEM_GEMM (2 * G2_STAGE)          // 73728

template <int MODE>
__global__ __launch_bounds__(256, 2) void gemm_f16(float* __restrict__ Cout)
{
    extern __shared__ __align__(16) char dsm[];
    const uint32_t sbase = smem_u32(dsm);

    const int tid  = threadIdx.x;
    const int wid  = tid >> 5;
    const int lane = tid & 31;
    const int wy = wid >> 2;
    const int wx = wid & 3;
    const int g = lane >> 2;
    const int t = lane & 3;
    const int m0 = blockIdx.y * 64;
    const int n0 = blockIdx.x * 128;

    const __half* __restrict__ Ah = (MODE == 0) ? g_in_fh : g_ctx_h;
    const __half* __restrict__ Al = (MODE == 0) ? g_in_fl : g_ctx_l;
    const __half* __restrict__ B  = (MODE == 0) ? g_win_f : g_wout;

    auto issue_stage = [&](int k0, uint32_t sb) {
#pragma unroll
        for (int u = 0; u < 2; u++) {                 // A: 64 rows x 8 chunks
            const int s = u * 256 + tid;
            const int r = s >> 3, ck = s & 7;
            const size_t ga = (size_t)(m0 + r) * KDIM + k0 + ck * 8;
            const uint32_t off = (uint32_t)(r * RSH + ck * 8) * 2;
            cp16(sb + off,         Ah + ga);
            cp16(sb + G2_AL + off, Al + ga);
        }
#pragma unroll
        for (int u = 0; u < 4; u++) {                 // B: 128 rows x 8 chunks
            const int s = u * 256 + tid;
            const int r = s >> 3, ck = s & 7;
            const size_t gb = (size_t)(n0 + r) * KDIM + k0 + ck * 8;
            const uint32_t off = (uint32_t)(r * RSH + ck * 8) * 2;
            cp16(sb + G2_B + off, B + gb);
        }
        CP_COMMIT();
    };

    float acc[2][4][4];
#pragma unroll
    for (int mi = 0; mi < 2; mi++)
#pragma unroll
        for (int nj = 0; nj < 4; nj++)
#pragma unroll
            for (int q = 0; q < 4; q++) acc[mi][nj][q] = 0.f;

    const int lrow = lane & 15;
    const int lcol = (lane >> 4) << 3;

    uint32_t fah[2][2][4], fal[2][2][4], fb[2][2][4];

    auto ldfrags = [&](uint32_t sb, int ks, int b) {
        const int kc = ks * 16 + lcol;
#pragma unroll
        for (int mi = 0; mi < 2; mi++) {
            const uint32_t ad = sb + ((wy * 32 + mi * 16 + lrow) * RSH + kc) * 2;
            ldsm_x4(fah[b][mi], ad);
            ldsm_x4(fal[b][mi], ad + G2_AL);
        }
#pragma unroll
        for (int p = 0; p < 2; p++) {
            const uint32_t bd = sb + G2_B + ((wx * 32 + p * 16 + lrow) * RSH + kc) * 2;
            ldsm_x4(fb[b][p], bd);
        }
    };
    auto docompute = [&](int b) {
#pragma unroll
        for (int mi = 0; mi < 2; mi++)
#pragma unroll
            for (int nj = 0; nj < 4; nj++) {
                const int p = nj >> 1, o = nj & 1;
                mma_f16(acc[mi][nj], fah[b][mi][0], fah[b][mi][1], fah[b][mi][2], fah[b][mi][3],
                        fb[b][p][o], fb[b][p][o + 2]);
                mma_f16(acc[mi][nj], fal[b][mi][0], fal[b][mi][1], fal[b][mi][2], fal[b][mi][3],
                        fb[b][p][o], fb[b][p][o + 2]);
            }
    };

    issue_stage(0, sbase);

    const int NIT = KDIM / 64;   // 16
    for (int i = 0; i < NIT; i++) {
        CP_WAIT(0);
        __syncthreads();
        const uint32_t sb = sbase + (i & 1) * G2_STAGE;
        ldfrags(sb, 0, 0);
        if (i + 1 < NIT)
            issue_stage((i + 1) * 64, sbase + ((i + 1) & 1) * G2_STAGE);
#pragma unroll
        for (int ks = 0; ks < 4; ks++) {
            if (ks < 3) ldfrags(sb, ks + 1, (ks + 1) & 1);
            docompute(ks & 1);
        }
    }

    // ---- epilogue
#pragma unroll
    for (int mi = 0; mi < 2; mi++) {
        const int row0 = m0 + wy * 32 + mi * 16 + g;
        const int row1 = row0 + 8;
#pragma unroll
        for (int nj = 0; nj < 4; nj++) {
            const int col = n0 + wx * 32 + nj * 8 + 2 * t;
            if (MODE == 1) {
                *(float2*)&Cout[(size_t)row0 * CDIM + col] =
                    make_float2(acc[mi][nj][0], acc[mi][nj][1]);
                *(float2*)&Cout[(size_t)row1 * CDIM + col] =
                    make_float2(acc[mi][nj][2], acc[mi][nj][3]);
            } else {
                const int which = col >> 10;
                __nv_bfloat16* dh = (which == 0) ? g_qh : ((which == 1) ? g_kh : g_vh);
                __nv_bfloat16* dl = (which == 0) ? g_ql : ((which == 1) ? g_kl : g_vl);
                const int hh = (col & 1023) >> 6;
                const int dd = col & 63;
                uint32_t hi, lo;
                pack_split2(acc[mi][nj][0], acc[mi][nj][1], hi, lo);
                {
                    const int br = row0 >> 11, lr2 = row0 & 2047;
                    const size_t idx = (((size_t)(br * NHEAD + hh)) * LSEQ + lr2) * DHEAD + dd;
                    *(uint32_t*)(dh + idx) = hi;
                    *(uint32_t*)(dl + idx) = lo;
                }
                pack_split2(acc[mi][nj][2], acc[mi][nj][3], hi, lo);
                {
                    const int br = row1 >> 11, lr2 = row1 & 2047;
                    const size_t idx = (((size_t)(br * NHEAD + hh)) * LSEQ + lr2) * DHEAD + dd;
                    *(uint32_t*)(dh + idx) = hi;
                    *(uint32_t*)(dl + idx) = lo;
                }
            }
        }
    }
}

// ---------------------------------------------------------------------------
// HMMA causal flash attention, 2-stage cp.async K/V pipeline, 2 CTAs/SM.
// (R9/R16 body; bf16 3-term QK + PV; ctx epilogue writes fp16 hi/lo)
// Br=128, Bc=64, 256 threads (8 warps). grid: (B*H, L/128) qtile reversed.
// ---------------------------------------------------------------------------
#define ARS 72
#define AQ_L 18432
#define AKV0 36864
#define A_KL 9216
#define A_VH 18432
#define A_VL 27648
#define A_STAGE 36864
#define SMEM_ATTN (AKV0 + 2 * A_STAGE)    // 110592

__global__ __launch_bounds__(256, 2) void attn_hmma()
{
    extern __shared__ __align__(16) char dsa[];
    const uint32_t sbase = smem_u32(dsa);

    const int tid  = threadIdx.x;
    const int w    = tid >> 5;
    const int lane = tid & 31;
    const int g = lane >> 2;
    const int t = lane & 3;
    const int lrow = lane & 15;
    const int lcol = (lane >> 4) << 3;

    const int bh = blockIdx.x;
    const int qt = (int)gridDim.y - 1 - (int)blockIdx.y;
    const int qbase = qt * 128;

    const size_t hoff = (size_t)bh * LSEQ * DHEAD;
    const __nv_bfloat16* __restrict__ Qh = g_qh + hoff;
    const __nv_bfloat16* __restrict__ Ql = g_ql + hoff;
    const __nv_bfloat16* __restrict__ Kh = g_kh + hoff;
    const __nv_bfloat16* __restrict__ Kl = g_kl + hoff;
    const __nv_bfloat16* __restrict__ Vh = g_vh + hoff;
    const __nv_bfloat16* __restrict__ Vl = g_vl + hoff;

    const int nkt = 2 * qt + 2;

    auto issue_kv = [&](int kt, uint32_t sb) {
#pragma unroll
        for (int it = 0; it < 2; it++) {
            const int s = it * 256 + tid;
            const int r = s >> 3, ck = s & 7;
            const size_t go = (size_t)(kt * 64 + r) * DHEAD + ck * 8;
            const uint32_t off = (uint32_t)(r * ARS + ck * 8) * 2;
            cp16(sb + off,        Kh + go);
            cp16(sb + A_KL + off, Kl + go);
            cp16(sb + A_VH + off, Vh + go);
            cp16(sb + A_VL + off, Vl + go);
        }
        CP_COMMIT();
    };

#pragma unroll
    for (int it = 0; it < 4; it++) {
        const int s = it * 256 + tid;
        const int r = s >> 3, ck = s & 7;
        const size_t go = (size_t)(qbase + r) * DHEAD + ck * 8;
        const uint32_t off = (uint32_t)(r * ARS + ck * 8) * 2;
        cp16(sbase + off,        Qh + go);
        cp16(sbase + AQ_L + off, Ql + go);
    }
    CP_COMMIT();
    issue_kv(0, sbase + AKV0);

    CP_WAIT(0);
    __syncthreads();
    uint32_t qfh[4][4], qfl[4][4];
#pragma unroll
    for (int ks = 0; ks < 4; ks++) {
        const uint32_t ad = sbase + ((w * 16 + lrow) * ARS + ks * 16 + lcol) * 2;
        ldsm_x4(qfh[ks], ad);
        ldsm_x4(qfl[ks], ad + AQ_L);
    }

    float O[8][4];
#pragma unroll
    for (int j = 0; j < 8; j++)
#pragma unroll
        for (int q = 0; q < 4; q++) O[j][q] = 0.f;
    float m0 = -1e30f, m1 = -1e30f, l0 = 0.f, l1 = 0.f;
    const float scale = 0.125f;
    const int row0 = qbase + w * 16 + g;
    const int row1 = row0 + 8;

    for (int kt = 0; kt < nkt; kt++) {
        const int kbase = kt * 64;

        CP_WAIT(0);
        __syncthreads();
        if (kt + 1 < nkt)
            issue_kv(kt + 1, sbase + AKV0 + ((kt + 1) & 1) * A_STAGE);

        const uint32_t sb = sbase + AKV0 + (kt & 1) * A_STAGE;

        float S[8][4];
#pragma unroll
        for (int j = 0; j < 8; j++)
#pragma unroll
            for (int q = 0; q < 4; q++) S[j][q] = 0.f;

#pragma unroll
        for (int ks = 0; ks < 4; ks++) {
#pragma unroll
            for (int p = 0; p < 4; p++) {
                uint32_t kh0[4], kl0[4];
                const uint32_t bd = sb + ((p * 16 + lrow) * ARS + ks * 16 + lcol) * 2;
                ldsm_x4(kh0, bd);
                ldsm_x4(kl0, bd + A_KL);
#pragma unroll
                for (int o = 0; o < 2; o++) {
                    const int j = 2 * p + o;
                    mma_bf16(S[j], qfh[ks][0], qfh[ks][1], qfh[ks][2], qfh[ks][3],
                             kh0[o], kh0[o + 2]);
                    mma_bf16(S[j], qfh[ks][0], qfh[ks][1], qfh[ks][2], qfh[ks][3],
                             kl0[o], kl0[o + 2]);
                    mma_bf16(S[j], qfl[ks][0], qfl[ks][1], qfl[ks][2], qfl[ks][3],
                             kh0[o], kh0[o + 2]);
                }
            }
        }

        if (kt >= nkt - 2) {
#pragma unroll
            for (int j = 0; j < 8; j++) {
                const int col = kbase + j * 8 + 2 * t;
                if (col > row0)     S[j][0] = -1e30f;
                if (col + 1 > row0) S[j][1] = -1e30f;
                if (col > row1)     S[j][2] = -1e30f;
                if (col + 1 > row1) S[j][3] = -1e30f;
            }
        }

        float mt0 = -1e30f, mt1 = -1e30f;
#pragma unroll
        for (int j = 0; j < 8; j++) {
            mt0 = fmaxf(mt0, fmaxf(S[j][0], S[j][1]));
            mt1 = fmaxf(mt1, fmaxf(S[j][2], S[j][3]));
        }
        mt0 = fmaxf(mt0, __shfl_xor_sync(0xffffffffu, mt0, 1));
        mt0 = fmaxf(mt0, __shfl_xor_sync(0xffffffffu, mt0, 2));
        mt1 = fmaxf(mt1, __shfl_xor_sync(0xffffffffu, mt1, 1));
        mt1 = fmaxf(mt1, __shfl_xor_sync(0xffffffffu, mt1, 2));
        const float mn0 = fmaxf(m0, mt0 * scale);
        const float mn1 = fmaxf(m1, mt1 * scale);
        const float a0 = __expf(m0 - mn0);
        const float a1 = __expf(m1 - mn1);
        m0 = mn0; m1 = mn1;

        float rs0 = 0.f, rs1 = 0.f;
#pragma unroll
        for (int j = 0; j < 8; j++) {
            S[j][0] = __expf(fmaf(S[j][0], scale, -mn0));
            S[j][1] = __expf(fmaf(S[j][1], scale, -mn0));
            S[j][2] = __expf(fmaf(S[j][2], scale, -mn1));
            S[j][3] = __expf(fmaf(S[j][3], scale, -mn1));
            rs0 += S[j][0] + S[j][1];
            rs1 += S[j][2] + S[j][3];
        }
        rs0 += __shfl_xor_sync(0xffffffffu, rs0, 1);
        rs0 += __shfl_xor_sync(0xffffffffu, rs0, 2);
        rs1 += __shfl_xor_sync(0xffffffffu, rs1, 1);
        rs1 += __shfl_xor_sync(0xffffffffu, rs1, 2);
        l0 = l0 * a0 + rs0;
        l1 = l1 * a1 + rs1;
#pragma unroll
        for (int j = 0; j < 8; j++) {
            O[j][0] *= a0; O[j][1] *= a0;
            O[j][2] *= a1; O[j][3] *= a1;
        }

#pragma unroll
        for (int jj = 0; jj < 4; jj++) {
            uint32_t ah[4], al[4];
            pack_split2(S[2 * jj][0],     S[2 * jj][1],     ah[0], al[0]);
            pack_split2(S[2 * jj][2],     S[2 * jj][3],     ah[1], al[1]);
            pack_split2(S[2 * jj + 1][0], S[2 * jj + 1][1], ah[2], al[2]);
            pack_split2(S[2 * jj + 1][2], S[2 * jj + 1][3], ah[3], al[3]);
#pragma unroll
            for (int p = 0; p < 4; p++) {
                uint32_t vh0[4], vl0[4];
                const uint32_t vd = sb + A_VH + ((jj * 16 + lrow) * ARS + p * 16 + lcol) * 2;
                ldsm_x4_t(vh0, vd);
                ldsm_x4_t(vl0, vd + (A_VL - A_VH));
#pragma unroll
                for (int o = 0; o < 2; o++) {
                    const int j2 = 2 * p + o;
                    mma_bf16(O[j2], ah[0], ah[1], ah[2], ah[3], vh0[2 * o], vh0[2 * o + 1]);
                    mma_bf16(O[j2], ah[0], ah[1], ah[2], ah[3], vl0[2 * o], vl0[2 * o + 1]);
                    mma_bf16(O[j2], al[0], al[1], al[2], al[3], vh0[2 * o], vh0[2 * o + 1]);
                }
            }
        }
    }

    // finalize + write ctx hi/lo fp16 [b*l][h*64+d]
    const int b = bh >> 4;
    const int h = bh & 15;
    const float i0 = 1.f / l0;
    const float i1 = 1.f / l1;
#pragma unroll
    for (int j = 0; j < 8; j++) {
        const int col = h * DHEAD + j * 8 + 2 * t;
        uint32_t hi, lo;
        pack_split2_f16(O[j][0] * i0, O[j][1] * i0, hi, lo);
        {
            const size_t idx = ((size_t)(b * LSEQ + row0)) * CDIM + col;
            *(uint32_t*)(g_ctx_h + idx) = hi;
            *(uint32_t*)(g_ctx_l + idx) = lo;
        }
        pack_split2_f16(O[j][2] * i1, O[j][3] * i1, hi, lo);
        {
            const size_t idx = ((size_t)(b * LSEQ + row1)) * CDIM + col;
            *(uint32_t*)(g_ctx_h + idx) = hi;
            *(uint32_t*)(g_ctx_l + idx) = lo;
        }
    }
}

// ---------------------------------------------------------------------------
extern "C" void kernel_launch(void* const* d_in, const int* in_sizes, int n_in,
                              void* d_out, int out_size)
{
    const float* input = (const float*)d_in[0];
    const float* w_in  = (const float*)d_in[1];
    const float* w_out = (const float*)d_in[2];
    float* out = (float*)d_out;

    cudaFuncSetAttribute(gemm_f16<0>, cudaFuncAttributeMaxDynamicSharedMemorySize, SMEM_GEMM);
    cudaFuncSetAttribute(gemm_f16<1>, cudaFuncAttributeMaxDynamicSharedMemorySize, SMEM_GEMM);
    cudaFuncSetAttribute(attn_hmma,   cudaFuncAttributeMaxDynamicSharedMemorySize, SMEM_ATTN);

    cvt_kernel<<<(CVT_TOTAL + 511) / 512, 256>>>(input, w_in, w_out);

    gemm_f16<0><<<dim3(3 * CDIM / 128, MROWS / 64), 256, SMEM_GEMM>>>(nullptr);
    attn_hmma<<<dim3(BATCH * NHEAD, LSEQ / 128), 256, SMEM_ATTN>>>();
    gemm_f16<1><<<dim3(CDIM / 128, MROWS / 64), 256, SMEM_GEMM>>>(out);
}